// round 6
// baseline (speedup 1.0000x reference)
#include <cuda_runtime.h>
#include <cuda_fp16.h>
#include <math.h>
#include <stdint.h>

// ---------------------------------------------------------------------------
// ForegroundAttentionModule, B=4, C=512, T=2048, fp32 in/out.
// fp16 mma.sync GEMMs (f32 accum), single product (validated rel_err ~4e-5).
// Algebra: key_ einsum collapses; q.k row-constant cancels in softmax -> kT
//   eliminated, wksum folded into q epilogue. z = colsum(v) - y.
// GEMM: D[M,N] = sum_K A[M,K]*B[N,K]. CTA 128x128, K chunk 32, 5-stage
// cp.async pipeline, ldmatrix x4 (A and paired-B), 8 warps (4M x 2N).
// Softmax: fp16x2 ex2 (1 MUFU / 2 elems), shfl reductions.
// ---------------------------------------------------------------------------

namespace {

constexpr int B = 4;
constexpr int C = 512;
constexpr int T = 2048;
constexpr float LN_EPS = 1e-5f;
constexpr float INV_SQRT_C = 0.04419417382415922f;

constexpr int ROW_BYTES   = 80;                  // 32 fp16 + 16B pad
constexpr int TILE_BYTES  = 128 * ROW_BYTES;     // 10240
constexpr int STAGE_BYTES = 2 * TILE_BYTES;      // A + B
constexpr int NSTAGES     = 5;
constexpr int SMEM_BYTES  = NSTAGES * STAGE_BYTES;  // 102400

// ---------------- device scratch -------------------------------------------
__device__ __half g_featT[(size_t)B * T * C];   // [B,T,C]
__device__ __half g_q[(size_t)B * T * C];       // [B,T,C] (pre-scaled by wksum)
__device__ __half g_vT[(size_t)B * C * T];      // [B,C,T]
__device__ __half g_y[(size_t)B * T * C];       // [B,T,C]
__device__ __half g_fh[(size_t)B * T * T];      // [B,T,T] logits -> probs
__device__ __half g_Wq[C * C], g_Wv[C * C], g_Ws[C * C];
__device__ float  g_wksum[C];
__device__ float  g_vsum[B * C];
__device__ float  g_vsumWl[B];
__device__ double g_lnsum[B], g_lnsq[B];

// ---------------- helpers ---------------------------------------------------
__device__ __forceinline__ void mma16816(float* c, uint32_t a0, uint32_t a1,
                                         uint32_t a2, uint32_t a3,
                                         uint32_t b0, uint32_t b1) {
    asm volatile(
        "mma.sync.aligned.m16n8k16.row.col.f32.f16.f16.f32 "
        "{%0,%1,%2,%3}, {%4,%5,%6,%7}, {%8,%9}, {%0,%1,%2,%3};"
        : "+f"(c[0]), "+f"(c[1]), "+f"(c[2]), "+f"(c[3])
        : "r"(a0), "r"(a1), "r"(a2), "r"(a3), "r"(b0), "r"(b1));
}

__device__ __forceinline__ void ldsm_x4(uint32_t& r0, uint32_t& r1,
                                        uint32_t& r2, uint32_t& r3, uint32_t addr) {
    asm volatile("ldmatrix.sync.aligned.m8n8.x4.shared.b16 {%0,%1,%2,%3}, [%4];"
                 : "=r"(r0), "=r"(r1), "=r"(r2), "=r"(r3) : "r"(addr));
}

__device__ __forceinline__ void cp_async16(uint32_t saddr, const void* g) {
    asm volatile("cp.async.cg.shared.global [%0], [%1], 16;" ::"r"(saddr), "l"(g));
}
__device__ __forceinline__ void cp_commit() {
    asm volatile("cp.async.commit_group;" ::: "memory");
}
template <int N>
__device__ __forceinline__ void cp_wait() {
    asm volatile("cp.async.wait_group %0;" ::"n"(N) : "memory");
}

// One 128x32 fp16 tile -> smem stage (2 x 16B per thread).
__device__ __forceinline__ void load_tile(const __half* __restrict__ src,
                                          int ld, int k0, uint32_t sbase, int tid) {
#pragma unroll
    for (int p = 0; p < 2; ++p) {
        int i = tid + p * 256;
        int row = i >> 2, q = i & 3;
        cp_async16(sbase + (uint32_t)(row * ROW_BYTES + q * 16),
                   src + (size_t)row * ld + k0 + q * 8);
    }
}

// ---------------------------------------------------------------------------
// GEMM mainloop: 5-stage pipeline, ldmatrix x4 everywhere, batched MMA runs.
// ---------------------------------------------------------------------------
__device__ __forceinline__ void gemm_mainloop(
    const __half* __restrict__ A, int ldA,
    const __half* __restrict__ Bm, int ldB,
    int kTotal, char* smem, float acc[2][8][4]) {
    const int tid = threadIdx.x;
    const int wid = tid >> 5, lane = tid & 31;
    const int wm = wid & 3, wn = wid >> 2;
    const uint32_t sbase = (uint32_t)__cvta_generic_to_shared(smem);
    const int nch = kTotal / 32;

    // A fragment base: rows wm*32 + (lane&15), halves by lane>>4
    const uint32_t aOff = (uint32_t)((wm * 32 + (lane & 15)) * ROW_BYTES + (lane >> 4) * 16);
    // B paired-x4 base: grp = lane>>3: m0/m1 = an(2j) k-halves, m2/m3 = an(2j+1)
    const int grp = lane >> 3;
    const uint32_t bOff = (uint32_t)(TILE_BYTES +
        (wn * 64 + (grp >> 1) * 8 + (lane & 7)) * ROW_BYTES + (grp & 1) * 16);

#pragma unroll
    for (int s = 0; s < 4; ++s) {
        load_tile(A,  ldA, s * 32, sbase + s * STAGE_BYTES, tid);
        load_tile(Bm, ldB, s * 32, sbase + s * STAGE_BYTES + TILE_BYTES, tid);
        cp_commit();
    }

    int s_use = 0, s_fill = 4;
    for (int kc = 0; kc < nch; ++kc) {
        cp_wait<3>();
        __syncthreads();
        if (kc + 4 < nch) {
            uint32_t st = sbase + (uint32_t)(s_fill * STAGE_BYTES);
            load_tile(A,  ldA, (kc + 4) * 32, st, tid);
            load_tile(Bm, ldB, (kc + 4) * 32, st + TILE_BYTES, tid);
        }
        cp_commit();

        const uint32_t sg = sbase + (uint32_t)(s_use * STAGE_BYTES);
#pragma unroll
        for (int ks = 0; ks < 2; ++ks) {
            uint32_t a0[4], a1[4];
            ldsm_x4(a0[0], a0[1], a0[2], a0[3], sg + aOff + ks * 32);
            ldsm_x4(a1[0], a1[1], a1[2], a1[3], sg + aOff + 16 * ROW_BYTES + ks * 32);
#pragma unroll
            for (int jp = 0; jp < 2; ++jp) {   // an blocks [4*jp, 4*jp+4)
                uint32_t bf[4][2];
                ldsm_x4(bf[0][0], bf[0][1], bf[1][0], bf[1][1],
                        sg + bOff + (jp * 2 + 0) * (16 * ROW_BYTES) + ks * 32);
                ldsm_x4(bf[2][0], bf[2][1], bf[3][0], bf[3][1],
                        sg + bOff + (jp * 2 + 1) * (16 * ROW_BYTES) + ks * 32);
#pragma unroll
                for (int j = 0; j < 4; ++j) {
                    const int an = jp * 4 + j;
                    mma16816(acc[0][an], a0[0], a0[1], a0[2], a0[3], bf[j][0], bf[j][1]);
                    mma16816(acc[1][an], a1[0], a1[1], a1[2], a1[3], bf[j][0], bf[j][1]);
                }
            }
        }
        if (++s_use == NSTAGES) s_use = 0;
        if (++s_fill == NSTAGES) s_fill = 0;
    }
}

#define EPI_COORDS()                                   \
    const int wid = threadIdx.x >> 5;                  \
    const int lane = threadIdx.x & 31;                 \
    const int wm = wid & 3, wn = wid >> 2;             \
    const int lr = lane >> 2, lc = lane & 3;

// ---------------------------------------------------------------------------
// GEMM kernels
// ---------------------------------------------------------------------------

// q'[b,t,o] = (featT @ Wq^T + bq) * wksum[o] -> fp16
__global__ __launch_bounds__(256, 2) void gemm_q_kernel(const float* __restrict__ bq) {
    extern __shared__ char smem[];
    const int b = blockIdx.z, t0 = blockIdx.x * 128, o0 = blockIdx.y * 128;
    float acc[2][8][4] = {};
    gemm_mainloop(g_featT + ((size_t)b * T + t0) * C, C,
                  g_Wq + (size_t)o0 * C, C, C, smem, acc);
    EPI_COORDS();
#pragma unroll
    for (int am = 0; am < 2; ++am) {
        const int t = t0 + wm * 32 + am * 16 + lr;
#pragma unroll
        for (int an = 0; an < 8; ++an) {
            const int o = o0 + wn * 64 + an * 8 + lc * 2;
            const float b0 = bq[o], b1 = bq[o + 1];
            const float w0 = g_wksum[o], w1 = g_wksum[o + 1];
#pragma unroll
            for (int rr = 0; rr < 2; ++rr) {
                const size_t idx = ((size_t)b * T + t + rr * 8) * C + o;
                *reinterpret_cast<__half2*>(&g_q[idx]) = __floats2half2_rn(
                    (acc[am][an][rr * 2] + b0) * w0,
                    (acc[am][an][rr * 2 + 1] + b1) * w1);
            }
        }
    }
}

// vT[b,o,t] = Wv @ featT^T + bv -> fp16
__global__ __launch_bounds__(256, 2) void gemm_vt_kernel(const float* __restrict__ bv) {
    extern __shared__ char smem[];
    const int b = blockIdx.z, t0 = blockIdx.x * 128, o0 = blockIdx.y * 128;
    float acc[2][8][4] = {};
    gemm_mainloop(g_Wv + (size_t)o0 * C, C,
                  g_featT + ((size_t)b * T + t0) * C, C, C, smem, acc);
    EPI_COORDS();
#pragma unroll
    for (int am = 0; am < 2; ++am) {
        const int o = o0 + wm * 32 + am * 16 + lr;
#pragma unroll
        for (int an = 0; an < 8; ++an) {
            const int t = t0 + wn * 64 + an * 8 + lc * 2;
#pragma unroll
            for (int rr = 0; rr < 2; ++rr) {
                const int oo = o + rr * 8;
                const float bo = bv[oo];
                const size_t idx = ((size_t)b * C + oo) * T + t;
                *reinterpret_cast<__half2*>(&g_vT[idx]) = __floats2half2_rn(
                    acc[am][an][rr * 2] + bo, acc[am][an][rr * 2 + 1] + bo);
            }
        }
    }
}

// logits f[b,t,s] = (q' @ featT^T) * inv_sqrt_c -> fp16
__global__ __launch_bounds__(256, 2) void gemm_qk_kernel() {
    extern __shared__ char smem[];
    const int b = blockIdx.z, s0 = blockIdx.x * 128, t0 = blockIdx.y * 128;
    float acc[2][8][4] = {};
    gemm_mainloop(g_q + ((size_t)b * T + t0) * C, C,
                  g_featT + ((size_t)b * T + s0) * C, C, C, smem, acc);
    EPI_COORDS();
#pragma unroll
    for (int am = 0; am < 2; ++am) {
        const int t = t0 + wm * 32 + am * 16 + lr;
#pragma unroll
        for (int an = 0; an < 8; ++an) {
            const int s = s0 + wn * 64 + an * 8 + lc * 2;
#pragma unroll
            for (int rr = 0; rr < 2; ++rr) {
                *reinterpret_cast<__half2*>(&g_fh[((size_t)b * T + t + rr * 8) * T + s]) =
                    __floats2half2_rn(acc[am][an][rr * 2] * INV_SQRT_C,
                                      acc[am][an][rr * 2 + 1] * INV_SQRT_C);
            }
        }
    }
}

// y[b,t,c] = f @ vT^T -> fp16
__global__ __launch_bounds__(256, 2) void gemm_av_kernel() {
    extern __shared__ char smem[];
    const int b = blockIdx.z, c0 = blockIdx.x * 128, t0 = blockIdx.y * 128;
    float acc[2][8][4] = {};
    gemm_mainloop(g_fh + ((size_t)b * T + t0) * T, T,
                  g_vT + ((size_t)b * C + c0) * T, T, T, smem, acc);
    EPI_COORDS();
#pragma unroll
    for (int am = 0; am < 2; ++am) {
        const int t = t0 + wm * 32 + am * 16 + lr;
#pragma unroll
        for (int an = 0; an < 8; ++an) {
            const int c = c0 + wn * 64 + an * 8 + lc * 2;
#pragma unroll
            for (int rr = 0; rr < 2; ++rr) {
                const size_t idx = ((size_t)b * T + t + rr * 8) * C + c;
                *reinterpret_cast<__half2*>(&g_y[idx]) =
                    __floats2half2_rn(acc[am][an][rr * 2], acc[am][an][rr * 2 + 1]);
            }
        }
    }
}

// out[b,o,t] = feat + Ws @ y^T + bs; fused LN pass-1 partials.
__global__ __launch_bounds__(256, 2) void gemm_smooth_kernel(const float* __restrict__ bs,
                                                             const float* __restrict__ feat,
                                                             float* __restrict__ out) {
    extern __shared__ char smem[];
    const int b = blockIdx.z, t0 = blockIdx.x * 128, o0 = blockIdx.y * 128;
    float acc[2][8][4] = {};
    gemm_mainloop(g_Ws + (size_t)o0 * C, C,
                  g_y + ((size_t)b * T + t0) * C, C, C, smem, acc);
    EPI_COORDS();
    float psum = 0.0f, psq = 0.0f;
#pragma unroll
    for (int am = 0; am < 2; ++am) {
        const int o = o0 + wm * 32 + am * 16 + lr;
#pragma unroll
        for (int an = 0; an < 8; ++an) {
            const int t = t0 + wn * 64 + an * 8 + lc * 2;
#pragma unroll
            for (int rr = 0; rr < 2; ++rr) {
                const int oo = o + rr * 8;
                const float bo = bs[oo];
                const size_t idx = ((size_t)b * C + oo) * T + t;
                float2 fv = *reinterpret_cast<const float2*>(&feat[idx]);
                float2 v;
                v.x = fv.x + acc[am][an][rr * 2] + bo;
                v.y = fv.y + acc[am][an][rr * 2 + 1] + bo;
                *reinterpret_cast<float2*>(&out[idx]) = v;
                psum += v.x + v.y;
                psq  += v.x * v.x + v.y * v.y;
            }
        }
    }
    __syncthreads();
    float* red = reinterpret_cast<float*>(smem);
#pragma unroll
    for (int off = 16; off > 0; off >>= 1) {
        psum += __shfl_xor_sync(0xFFFFFFFFu, psum, off);
        psq  += __shfl_xor_sync(0xFFFFFFFFu, psq,  off);
    }
    if (lane == 0) { red[wid] = psum; red[8 + wid] = psq; }
    __syncthreads();
    if (threadIdx.x == 0) {
        float s = 0.0f, q = 0.0f;
#pragma unroll
        for (int w = 0; w < 8; ++w) { s += red[w]; q += red[8 + w]; }
        atomicAdd(&g_lnsum[b], (double)s);
        atomicAdd(&g_lnsq[b],  (double)q);
    }
}

// ---------------------------------------------------------------------------
// Elementwise / reduction kernels
// ---------------------------------------------------------------------------
__global__ void wksum_kernel(const float* __restrict__ Wk) {
    int c = blockIdx.x * 256 + threadIdx.x;
    if (c < B && blockIdx.x == 0) { g_lnsum[c] = 0.0; g_lnsq[c] = 0.0; }
    if (c >= C) return;
    float s = 0.0f;
    for (int o = 0; o < C; ++o) s += Wk[(size_t)o * C + c];
    g_wksum[c] = s;
}

// feat [B,C,T] -> featT fp16 [B,T,C]
__global__ void transpose_kernel(const float* __restrict__ feat) {
    __shared__ float tile[32][33];
    const int b = blockIdx.z;
    const int t0 = blockIdx.x * 32, c0 = blockIdx.y * 32;
    const int tx = threadIdx.x, ty = threadIdx.y;
#pragma unroll
    for (int i = 0; i < 4; ++i)
        tile[ty + 8 * i][tx] = feat[((size_t)b * C + c0 + ty + 8 * i) * T + t0 + tx];
    __syncthreads();
    const int c = c0 + tx;
#pragma unroll
    for (int i = 0; i < 4; ++i) {
        const int t = t0 + ty + 8 * i;
        g_featT[((size_t)b * T + t) * C + c] = __float2half_rn(tile[tx][ty + 8 * i]);
    }
}

__global__ void convertw_kernel(const float* __restrict__ Wq,
                                const float* __restrict__ Wv,
                                const float* __restrict__ Ws) {
    int i = blockIdx.x * 256 + threadIdx.x;
    if (i >= C * C) return;
    g_Wq[i] = __float2half_rn(Wq[i]);
    g_Wv[i] = __float2half_rn(Wv[i]);
    g_Ws[i] = __float2half_rn(Ws[i]);
}

// Row softmax: fp16x2 pipeline, ex2.f16x2 (1 MUFU / 2 elems), shfl reductions.
__global__ __launch_bounds__(256) void softmax_kernel() {
    __shared__ __half2 buf[T / 2];
    __shared__ float red[8];
    const int tid = threadIdx.x, lane = tid & 31, wrp = tid >> 5;
    __half2* row = reinterpret_cast<__half2*>(g_fh) + (size_t)blockIdx.x * (T / 2);

    float m = -1e30f;
    for (int i = tid; i < T / 2; i += 256) {
        __half2 h = row[i];
        buf[i] = h;
        float2 f = __half22float2(h);
        m = fmaxf(m, fmaxf(f.x, f.y));
    }
#pragma unroll
    for (int off = 16; off > 0; off >>= 1)
        m = fmaxf(m, __shfl_xor_sync(0xFFFFFFFFu, m, off));
    if (lane == 0) red[wrp] = m;
    __syncthreads();
    m = red[0];
#pragma unroll
    for (int w = 1; w < 8; ++w) m = fmaxf(m, red[w]);
    const __half2 m2 = __float2half2_rn(m);
    const __half2 l2e = __float2half2_rn(1.44269504f);

    float s = 0.0f;
    for (int i = tid; i < T / 2; i += 256) {
        __half2 e = h2exp2(__hmul2(__hsub2(buf[i], m2), l2e));
        buf[i] = e;
        float2 f = __half22float2(e);
        s += f.x + f.y;
    }
#pragma unroll
    for (int off = 16; off > 0; off >>= 1)
        s += __shfl_xor_sync(0xFFFFFFFFu, s, off);
    __syncthreads();
    if (lane == 0) red[wrp] = s;
    __syncthreads();
    s = 0.0f;
#pragma unroll
    for (int w = 0; w < 8; ++w) s += red[w];
    const __half2 inv2 = __float2half2_rn(1.0f / s);
    for (int i = tid; i < T / 2; i += 256)
        row[i] = __hmul2(buf[i], inv2);
}

__global__ void vsum_kernel() {
    __shared__ float red[256];
    const int c = blockIdx.x, b = blockIdx.y, tid = threadIdx.x;
    const __half* p = g_vT + ((size_t)b * C + c) * T;
    float s = 0.0f;
    for (int t = tid; t < T; t += 256) s += __half2float(p[t]);
    red[tid] = s;
    __syncthreads();
    for (int off = 128; off > 0; off >>= 1) {
        if (tid < off) red[tid] += red[tid + off];
        __syncthreads();
    }
    if (tid == 0) g_vsum[b * C + c] = red[0];
}

__global__ void vsumwl_kernel(const float* __restrict__ Wl) {
    __shared__ float red[128];
    const int b = blockIdx.x, tid = threadIdx.x;
    float s = 0.0f;
    for (int c = tid; c < C; c += 128) s += g_vsum[b * C + c] * Wl[c];
    red[tid] = s;
    __syncthreads();
    for (int off = 64; off > 0; off >>= 1) {
        if (tid < off) red[tid] += red[tid + off];
        __syncthreads();
    }
    if (tid == 0) g_vsumWl[b] = red[0];
}

__global__ void score_kernel(const float* __restrict__ Wl,
                             const float* __restrict__ bl,
                             float* __restrict__ score) {
    __shared__ float red[128];
    const int row = blockIdx.x;  // b*T + t
    const int b = row / T;
    const int tid = threadIdx.x;
    const __half* yr = g_y + (size_t)row * C;
    float s = 0.0f;
    for (int c = tid; c < C; c += 128) s += __half2float(yr[c]) * Wl[c];
    red[tid] = s;
    __syncthreads();
    for (int off = 64; off > 0; off >>= 1) {
        if (tid < off) red[tid] += red[tid + off];
        __syncthreads();
    }
    if (tid == 0) {
        float yl = red[0];
        float zl = g_vsumWl[b] - yl;
        float b0 = bl[0];
        float fs = 1.0f / (1.0f + expf(-(yl + b0)));
        float bsc = 1.0f - 1.0f / (1.0f + expf(-(zl + b0)));
        score[row] = 0.5f * (fs + bsc);
    }
}

__global__ void ln2_kernel(float* __restrict__ out) {
    const int b = blockIdx.y;
    const int i = blockIdx.x * 256 + threadIdx.x;
    const double n = (double)(C * T);
    double mu = g_lnsum[b] / n;
    double var = g_lnsq[b] / n - mu * mu;
    float muf = (float)mu;
    float inv = rsqrtf((float)var + LN_EPS);
    size_t oi = (size_t)b * C * T + i;
    out[oi] = (out[oi] - muf) * inv;
}

}  // namespace

// ---------------------------------------------------------------------------
extern "C" void kernel_launch(void* const* d_in, const int* in_sizes, int n_in,
                              void* d_out, int out_size) {
    const float* feat = (const float*)d_in[0];
    const float* Wq   = (const float*)d_in[1];
    const float* bq   = (const float*)d_in[2];
    const float* Wk   = (const float*)d_in[3];
    const float* bk   = (const float*)d_in[4];  // unused: cancels in softmax
    const float* Wv   = (const float*)d_in[5];
    const float* bv   = (const float*)d_in[6];
    const float* Ws   = (const float*)d_in[7];
    const float* bs   = (const float*)d_in[8];
    const float* Wl   = (const float*)d_in[9];
    const float* bl   = (const float*)d_in[10];
    float* out = (float*)d_out;
    float* score = out + (size_t)B * C * T;
    (void)bk;

    cudaFuncSetAttribute(gemm_q_kernel,      cudaFuncAttributeMaxDynamicSharedMemorySize, SMEM_BYTES);
    cudaFuncSetAttribute(gemm_vt_kernel,     cudaFuncAttributeMaxDynamicSharedMemorySize, SMEM_BYTES);
    cudaFuncSetAttribute(gemm_qk_kernel,     cudaFuncAttributeMaxDynamicSharedMemorySize, SMEM_BYTES);
    cudaFuncSetAttribute(gemm_av_kernel,     cudaFuncAttributeMaxDynamicSharedMemorySize, SMEM_BYTES);
    cudaFuncSetAttribute(gemm_smooth_kernel, cudaFuncAttributeMaxDynamicSharedMemorySize, SMEM_BYTES);

    wksum_kernel<<<2, 256>>>(Wk);
    transpose_kernel<<<dim3(T / 32, C / 32, B), dim3(32, 8)>>>(feat);
    convertw_kernel<<<(C * C + 255) / 256, 256>>>(Wq, Wv, Ws);

    gemm_q_kernel<<<dim3(T / 128, C / 128, B), 256, SMEM_BYTES>>>(bq);
    gemm_vt_kernel<<<dim3(T / 128, C / 128, B), 256, SMEM_BYTES>>>(bv);
    gemm_qk_kernel<<<dim3(T / 128, T / 128, B), 256, SMEM_BYTES>>>();
    softmax_kernel<<<B * T, 256>>>();
    gemm_av_kernel<<<dim3(C / 128, T / 128, B), 256, SMEM_BYTES>>>();

    vsum_kernel<<<dim3(C, B), 256>>>();
    vsumwl_kernel<<<B, 128>>>(Wl);
    score_kernel<<<B * T, 128>>>(Wl, bl, score);

    gemm_smooth_kernel<<<dim3(T / 128, C / 128, B), 256, SMEM_BYTES>>>(bs, feat, out);

    ln2_kernel<<<dim3((C * T) / 256, B), 256>>>(out);
}

// round 7
// speedup vs baseline: 1.4895x; 1.4895x over previous
#include <cuda_runtime.h>
#include <cuda_fp16.h>
#include <math.h>
#include <stdint.h>

// ---------------------------------------------------------------------------
// ForegroundAttentionModule, B=4, C=512, T=2048, fp32 in/out.
// fp16 mma.sync GEMMs (f32 accum), single product (validated rel_err ~4e-5).
// Algebra: key_ einsum collapses; q.k row-constant cancels in softmax -> kT
//   eliminated, wksum folded into q epilogue. z = colsum(v) - y.
// GEMM (Round-5 proven config): CTA 128x128, K chunk 32, 4-stage cp.async
// pipeline (prefetch 3, wait<2>), ldmatrix x4 A / x2 B, 8 warps (4M x 2N).
// q and vT projections merged into one launch (same shape, z selects).
// Softmax: fp16x2 ex2 (1 MUFU / 2 elems), shfl reductions.
// ---------------------------------------------------------------------------

namespace {

constexpr int B = 4;
constexpr int C = 512;
constexpr int T = 2048;
constexpr float LN_EPS = 1e-5f;
constexpr float INV_SQRT_C = 0.04419417382415922f;

constexpr int ROW_BYTES   = 80;                  // 32 fp16 + 16B pad
constexpr int TILE_BYTES  = 128 * ROW_BYTES;     // 10240
constexpr int STAGE_BYTES = 2 * TILE_BYTES;      // A + B
constexpr int NSTAGES     = 4;
constexpr int SMEM_BYTES  = NSTAGES * STAGE_BYTES;  // 81920

// ---------------- device scratch -------------------------------------------
__device__ __half g_featT[(size_t)B * T * C];   // [B,T,C]
__device__ __half g_q[(size_t)B * T * C];       // [B,T,C] (pre-scaled by wksum)
__device__ __half g_vT[(size_t)B * C * T];      // [B,C,T]
__device__ __half g_y[(size_t)B * T * C];       // [B,T,C]
__device__ __half g_fh[(size_t)B * T * T];      // [B,T,T] logits -> probs
__device__ __half g_Wq[C * C], g_Wv[C * C], g_Ws[C * C];
__device__ float  g_wksum[C];
__device__ float  g_vsum[B * C];
__device__ float  g_vsumWl[B];
__device__ double g_lnsum[B], g_lnsq[B];

// ---------------- helpers ---------------------------------------------------
__device__ __forceinline__ void mma16816(float* c, uint32_t a0, uint32_t a1,
                                         uint32_t a2, uint32_t a3,
                                         uint32_t b0, uint32_t b1) {
    asm volatile(
        "mma.sync.aligned.m16n8k16.row.col.f32.f16.f16.f32 "
        "{%0,%1,%2,%3}, {%4,%5,%6,%7}, {%8,%9}, {%0,%1,%2,%3};"
        : "+f"(c[0]), "+f"(c[1]), "+f"(c[2]), "+f"(c[3])
        : "r"(a0), "r"(a1), "r"(a2), "r"(a3), "r"(b0), "r"(b1));
}

__device__ __forceinline__ void ldsm_x4(uint32_t& r0, uint32_t& r1,
                                        uint32_t& r2, uint32_t& r3, uint32_t addr) {
    asm volatile("ldmatrix.sync.aligned.m8n8.x4.shared.b16 {%0,%1,%2,%3}, [%4];"
                 : "=r"(r0), "=r"(r1), "=r"(r2), "=r"(r3) : "r"(addr));
}
__device__ __forceinline__ void ldsm_x2(uint32_t& r0, uint32_t& r1, uint32_t addr) {
    asm volatile("ldmatrix.sync.aligned.m8n8.x2.shared.b16 {%0,%1}, [%2];"
                 : "=r"(r0), "=r"(r1) : "r"(addr));
}

__device__ __forceinline__ void cp_async16(uint32_t saddr, const void* g) {
    asm volatile("cp.async.cg.shared.global [%0], [%1], 16;" ::"r"(saddr), "l"(g));
}
__device__ __forceinline__ void cp_commit() {
    asm volatile("cp.async.commit_group;" ::: "memory");
}
template <int N>
__device__ __forceinline__ void cp_wait() {
    asm volatile("cp.async.wait_group %0;" ::"n"(N) : "memory");
}

// One 128x32 fp16 tile -> smem stage (2 x 16B per thread).
__device__ __forceinline__ void load_tile(const __half* __restrict__ src,
                                          int ld, int k0, uint32_t sbase, int tid) {
#pragma unroll
    for (int p = 0; p < 2; ++p) {
        int i = tid + p * 256;
        int row = i >> 2, q = i & 3;
        cp_async16(sbase + (uint32_t)(row * ROW_BYTES + q * 16),
                   src + (size_t)row * ld + k0 + q * 8);
    }
}

// ---------------------------------------------------------------------------
// GEMM mainloop (Round-5 proven): 4-stage pipeline, ldmatrix fragments.
// ---------------------------------------------------------------------------
__device__ __forceinline__ void gemm_mainloop(
    const __half* __restrict__ A, int ldA,
    const __half* __restrict__ Bm, int ldB,
    int kTotal, char* smem, float acc[2][8][4]) {
    const int tid = threadIdx.x;
    const int wid = tid >> 5, lane = tid & 31;
    const int wm = wid & 3, wn = wid >> 2;
    const uint32_t sbase = (uint32_t)__cvta_generic_to_shared(smem);
    const int nch = kTotal / 32;

    const uint32_t aOff = (uint32_t)((wm * 32 + (lane & 15)) * ROW_BYTES + (lane >> 4) * 16);
    const uint32_t bOff = (uint32_t)(TILE_BYTES +
                          (wn * 64 + (lane & 7)) * ROW_BYTES + ((lane >> 3) & 1) * 16);

#pragma unroll
    for (int s = 0; s < 3; ++s) {
        load_tile(A,  ldA, s * 32, sbase + s * STAGE_BYTES, tid);
        load_tile(Bm, ldB, s * 32, sbase + s * STAGE_BYTES + TILE_BYTES, tid);
        cp_commit();
    }

    for (int kc = 0; kc < nch; ++kc) {
        cp_wait<2>();
        __syncthreads();
        if (kc + 3 < nch) {
            uint32_t st = sbase + (uint32_t)(((kc + 3) & 3) * STAGE_BYTES);
            load_tile(A,  ldA, (kc + 3) * 32, st, tid);
            load_tile(Bm, ldB, (kc + 3) * 32, st + TILE_BYTES, tid);
        }
        cp_commit();

        const uint32_t sg = sbase + (uint32_t)((kc & 3) * STAGE_BYTES);
#pragma unroll
        for (int ks = 0; ks < 2; ++ks) {
            uint32_t a[2][4];
            ldsm_x4(a[0][0], a[0][1], a[0][2], a[0][3], sg + aOff + ks * 32);
            ldsm_x4(a[1][0], a[1][1], a[1][2], a[1][3], sg + aOff + 16 * ROW_BYTES + ks * 32);
#pragma unroll
            for (int an = 0; an < 8; ++an) {
                uint32_t b0, b1;
                ldsm_x2(b0, b1, sg + bOff + an * 8 * ROW_BYTES + ks * 32);
                mma16816(acc[0][an], a[0][0], a[0][1], a[0][2], a[0][3], b0, b1);
                mma16816(acc[1][an], a[1][0], a[1][1], a[1][2], a[1][3], b0, b1);
            }
        }
    }
}

#define EPI_COORDS()                                   \
    const int wid = threadIdx.x >> 5;                  \
    const int lane = threadIdx.x & 31;                 \
    const int wm = wid & 3, wn = wid >> 2;             \
    const int lr = lane >> 2, lc = lane & 3;

// ---------------------------------------------------------------------------
// GEMM kernels
// ---------------------------------------------------------------------------

// Merged projections. z = b + B*which: which=0 -> q', which=1 -> vT.
//   q'[b,t,o] = (featT @ Wq^T + bq) * wksum[o]
//   vT[b,o,t] = Wv @ featT^T + bv
__global__ __launch_bounds__(256, 2) void gemm_qv_kernel(const float* __restrict__ bq,
                                                         const float* __restrict__ bv) {
    extern __shared__ char smem[];
    const int b = blockIdx.z & (B - 1), which = blockIdx.z >> 2;
    const int t0 = blockIdx.x * 128, o0 = blockIdx.y * 128;
    float acc[2][8][4] = {};
    if (which == 0) {
        gemm_mainloop(g_featT + ((size_t)b * T + t0) * C, C,
                      g_Wq + (size_t)o0 * C, C, C, smem, acc);
    } else {
        gemm_mainloop(g_Wv + (size_t)o0 * C, C,
                      g_featT + ((size_t)b * T + t0) * C, C, C, smem, acc);
    }
    EPI_COORDS();
    if (which == 0) {
#pragma unroll
        for (int am = 0; am < 2; ++am) {
            const int t = t0 + wm * 32 + am * 16 + lr;
#pragma unroll
            for (int an = 0; an < 8; ++an) {
                const int o = o0 + wn * 64 + an * 8 + lc * 2;
                const float b0 = bq[o], b1 = bq[o + 1];
                const float w0 = g_wksum[o], w1 = g_wksum[o + 1];
#pragma unroll
                for (int rr = 0; rr < 2; ++rr) {
                    const size_t idx = ((size_t)b * T + t + rr * 8) * C + o;
                    *reinterpret_cast<__half2*>(&g_q[idx]) = __floats2half2_rn(
                        (acc[am][an][rr * 2] + b0) * w0,
                        (acc[am][an][rr * 2 + 1] + b1) * w1);
                }
            }
        }
    } else {
#pragma unroll
        for (int am = 0; am < 2; ++am) {
            const int o = o0 + wm * 32 + am * 16 + lr;
#pragma unroll
            for (int an = 0; an < 8; ++an) {
                const int t = t0 + wn * 64 + an * 8 + lc * 2;
#pragma unroll
                for (int rr = 0; rr < 2; ++rr) {
                    const int oo = o + rr * 8;
                    const float bo = bv[oo];
                    const size_t idx = ((size_t)b * C + oo) * T + t;
                    *reinterpret_cast<__half2*>(&g_vT[idx]) = __floats2half2_rn(
                        acc[am][an][rr * 2] + bo, acc[am][an][rr * 2 + 1] + bo);
                }
            }
        }
    }
}

// logits f[b,t,s] = (q' @ featT^T) * inv_sqrt_c -> fp16
__global__ __launch_bounds__(256, 2) void gemm_qk_kernel() {
    extern __shared__ char smem[];
    const int b = blockIdx.z, s0 = blockIdx.x * 128, t0 = blockIdx.y * 128;
    float acc[2][8][4] = {};
    gemm_mainloop(g_q + ((size_t)b * T + t0) * C, C,
                  g_featT + ((size_t)b * T + s0) * C, C, C, smem, acc);
    EPI_COORDS();
#pragma unroll
    for (int am = 0; am < 2; ++am) {
        const int t = t0 + wm * 32 + am * 16 + lr;
#pragma unroll
        for (int an = 0; an < 8; ++an) {
            const int s = s0 + wn * 64 + an * 8 + lc * 2;
#pragma unroll
            for (int rr = 0; rr < 2; ++rr) {
                *reinterpret_cast<__half2*>(&g_fh[((size_t)b * T + t + rr * 8) * T + s]) =
                    __floats2half2_rn(acc[am][an][rr * 2] * INV_SQRT_C,
                                      acc[am][an][rr * 2 + 1] * INV_SQRT_C);
            }
        }
    }
}

// y[b,t,c] = f @ vT^T -> fp16
__global__ __launch_bounds__(256, 2) void gemm_av_kernel() {
    extern __shared__ char smem[];
    const int b = blockIdx.z, c0 = blockIdx.x * 128, t0 = blockIdx.y * 128;
    float acc[2][8][4] = {};
    gemm_mainloop(g_fh + ((size_t)b * T + t0) * T, T,
                  g_vT + ((size_t)b * C + c0) * T, T, T, smem, acc);
    EPI_COORDS();
#pragma unroll
    for (int am = 0; am < 2; ++am) {
        const int t = t0 + wm * 32 + am * 16 + lr;
#pragma unroll
        for (int an = 0; an < 8; ++an) {
            const int c = c0 + wn * 64 + an * 8 + lc * 2;
#pragma unroll
            for (int rr = 0; rr < 2; ++rr) {
                const size_t idx = ((size_t)b * T + t + rr * 8) * C + c;
                *reinterpret_cast<__half2*>(&g_y[idx]) =
                    __floats2half2_rn(acc[am][an][rr * 2], acc[am][an][rr * 2 + 1]);
            }
        }
    }
}

// out[b,o,t] = feat + Ws @ y^T + bs; fused LN pass-1 partials.
__global__ __launch_bounds__(256, 2) void gemm_smooth_kernel(const float* __restrict__ bs,
                                                             const float* __restrict__ feat,
                                                             float* __restrict__ out) {
    extern __shared__ char smem[];
    const int b = blockIdx.z, t0 = blockIdx.x * 128, o0 = blockIdx.y * 128;
    float acc[2][8][4] = {};
    gemm_mainloop(g_Ws + (size_t)o0 * C, C,
                  g_y + ((size_t)b * T + t0) * C, C, C, smem, acc);
    EPI_COORDS();
    float psum = 0.0f, psq = 0.0f;
#pragma unroll
    for (int am = 0; am < 2; ++am) {
        const int o = o0 + wm * 32 + am * 16 + lr;
#pragma unroll
        for (int an = 0; an < 8; ++an) {
            const int t = t0 + wn * 64 + an * 8 + lc * 2;
#pragma unroll
            for (int rr = 0; rr < 2; ++rr) {
                const int oo = o + rr * 8;
                const float bo = bs[oo];
                const size_t idx = ((size_t)b * C + oo) * T + t;
                float2 fv = *reinterpret_cast<const float2*>(&feat[idx]);
                float2 v;
                v.x = fv.x + acc[am][an][rr * 2] + bo;
                v.y = fv.y + acc[am][an][rr * 2 + 1] + bo;
                *reinterpret_cast<float2*>(&out[idx]) = v;
                psum += v.x + v.y;
                psq  += v.x * v.x + v.y * v.y;
            }
        }
    }
    __syncthreads();
    float* red = reinterpret_cast<float*>(smem);
#pragma unroll
    for (int off = 16; off > 0; off >>= 1) {
        psum += __shfl_xor_sync(0xFFFFFFFFu, psum, off);
        psq  += __shfl_xor_sync(0xFFFFFFFFu, psq,  off);
    }
    if (lane == 0) { red[wid] = psum; red[8 + wid] = psq; }
    __syncthreads();
    if (threadIdx.x == 0) {
        float s = 0.0f, q = 0.0f;
#pragma unroll
        for (int w = 0; w < 8; ++w) { s += red[w]; q += red[8 + w]; }
        atomicAdd(&g_lnsum[b], (double)s);
        atomicAdd(&g_lnsq[b],  (double)q);
    }
}

// ---------------------------------------------------------------------------
// Elementwise / reduction kernels
// ---------------------------------------------------------------------------
__global__ void wksum_kernel(const float* __restrict__ Wk) {
    int c = blockIdx.x * 256 + threadIdx.x;
    if (c < B && blockIdx.x == 0) { g_lnsum[c] = 0.0; g_lnsq[c] = 0.0; }
    if (c >= C) return;
    float s = 0.0f;
    for (int o = 0; o < C; ++o) s += Wk[(size_t)o * C + c];
    g_wksum[c] = s;
}

// feat [B,C,T] -> featT fp16 [B,T,C]
__global__ void transpose_kernel(const float* __restrict__ feat) {
    __shared__ float tile[32][33];
    const int b = blockIdx.z;
    const int t0 = blockIdx.x * 32, c0 = blockIdx.y * 32;
    const int tx = threadIdx.x, ty = threadIdx.y;
#pragma unroll
    for (int i = 0; i < 4; ++i)
        tile[ty + 8 * i][tx] = feat[((size_t)b * C + c0 + ty + 8 * i) * T + t0 + tx];
    __syncthreads();
    const int c = c0 + tx;
#pragma unroll
    for (int i = 0; i < 4; ++i) {
        const int t = t0 + ty + 8 * i;
        g_featT[((size_t)b * T + t) * C + c] = __float2half_rn(tile[tx][ty + 8 * i]);
    }
}

__global__ void convertw_kernel(const float* __restrict__ Wq,
                                const float* __restrict__ Wv,
                                const float* __restrict__ Ws) {
    int i = blockIdx.x * 256 + threadIdx.x;
    if (i >= C * C) return;
    g_Wq[i] = __float2half_rn(Wq[i]);
    g_Wv[i] = __float2half_rn(Wv[i]);
    g_Ws[i] = __float2half_rn(Ws[i]);
}

// Row softmax: fp16x2 pipeline, ex2.f16x2, shfl reductions.
__global__ __launch_bounds__(256) void softmax_kernel() {
    __shared__ __half2 buf[T / 2];
    __shared__ float red[8];
    const int tid = threadIdx.x, lane = tid & 31, wrp = tid >> 5;
    __half2* row = reinterpret_cast<__half2*>(g_fh) + (size_t)blockIdx.x * (T / 2);

    float m = -1e30f;
    for (int i = tid; i < T / 2; i += 256) {
        __half2 h = row[i];
        buf[i] = h;
        float2 f = __half22float2(h);
        m = fmaxf(m, fmaxf(f.x, f.y));
    }
#pragma unroll
    for (int off = 16; off > 0; off >>= 1)
        m = fmaxf(m, __shfl_xor_sync(0xFFFFFFFFu, m, off));
    if (lane == 0) red[wrp] = m;
    __syncthreads();
    m = red[0];
#pragma unroll
    for (int w = 1; w < 8; ++w) m = fmaxf(m, red[w]);
    const __half2 m2 = __float2half2_rn(m);
    const __half2 l2e = __float2half2_rn(1.44269504f);

    float s = 0.0f;
    for (int i = tid; i < T / 2; i += 256) {
        __half2 e = h2exp2(__hmul2(__hsub2(buf[i], m2), l2e));
        buf[i] = e;
        float2 f = __half22float2(e);
        s += f.x + f.y;
    }
#pragma unroll
    for (int off = 16; off > 0; off >>= 1)
        s += __shfl_xor_sync(0xFFFFFFFFu, s, off);
    __syncthreads();
    if (lane == 0) red[wrp] = s;
    __syncthreads();
    s = 0.0f;
#pragma unroll
    for (int w = 0; w < 8; ++w) s += red[w];
    const __half2 inv2 = __float2half2_rn(1.0f / s);
    for (int i = tid; i < T / 2; i += 256)
        row[i] = __hmul2(buf[i], inv2);
}

__global__ void vsum_kernel() {
    __shared__ float red[256];
    const int c = blockIdx.x, b = blockIdx.y, tid = threadIdx.x;
    const __half* p = g_vT + ((size_t)b * C + c) * T;
    float s = 0.0f;
    for (int t = tid; t < T; t += 256) s += __half2float(p[t]);
    red[tid] = s;
    __syncthreads();
    for (int off = 128; off > 0; off >>= 1) {
        if (tid < off) red[tid] += red[tid + off];
        __syncthreads();
    }
    if (tid == 0) g_vsum[b * C + c] = red[0];
}

__global__ void vsumwl_kernel(const float* __restrict__ Wl) {
    __shared__ float red[128];
    const int b = blockIdx.x, tid = threadIdx.x;
    float s = 0.0f;
    for (int c = tid; c < C; c += 128) s += g_vsum[b * C + c] * Wl[c];
    red[tid] = s;
    __syncthreads();
    for (int off = 64; off > 0; off >>= 1) {
        if (tid < off) red[tid] += red[tid + off];
        __syncthreads();
    }
    if (tid == 0) g_vsumWl[b] = red[0];
}

__global__ void score_kernel(const float* __restrict__ Wl,
                             const float* __restrict__ bl,
                             float* __restrict__ score) {
    __shared__ float red[128];
    const int row = blockIdx.x;  // b*T + t
    const int b = row / T;
    const int tid = threadIdx.x;
    const __half* yr = g_y + (size_t)row * C;
    float s = 0.0f;
    for (int c = tid; c < C; c += 128) s += __half2float(yr[c]) * Wl[c];
    red[tid] = s;
    __syncthreads();
    for (int off = 64; off > 0; off >>= 1) {
        if (tid < off) red[tid] += red[tid + off];
        __syncthreads();
    }
    if (tid == 0) {
        float yl = red[0];
        float zl = g_vsumWl[b] - yl;
        float b0 = bl[0];
        float fs = 1.0f / (1.0f + expf(-(yl + b0)));
        float bsc = 1.0f - 1.0f / (1.0f + expf(-(zl + b0)));
        score[row] = 0.5f * (fs + bsc);
    }
}

__global__ void ln2_kernel(float* __restrict__ out) {
    const int b = blockIdx.y;
    const int i = blockIdx.x * 256 + threadIdx.x;
    const double n = (double)(C * T);
    double mu = g_lnsum[b] / n;
    double var = g_lnsq[b] / n - mu * mu;
    float muf = (float)mu;
    float inv = rsqrtf((float)var + LN_EPS);
    size_t oi = (size_t)b * C * T + i;
    out[oi] = (out[oi] - muf) * inv;
}

}  // namespace

// ---------------------------------------------------------------------------
extern "C" void kernel_launch(void* const* d_in, const int* in_sizes, int n_in,
                              void* d_out, int out_size) {
    const float* feat = (const float*)d_in[0];
    const float* Wq   = (const float*)d_in[1];
    const float* bq   = (const float*)d_in[2];
    const float* Wk   = (const float*)d_in[3];
    const float* bk   = (const float*)d_in[4];  // unused: cancels in softmax
    const float* Wv   = (const float*)d_in[5];
    const float* bv   = (const float*)d_in[6];
    const float* Ws   = (const float*)d_in[7];
    const float* bs   = (const float*)d_in[8];
    const float* Wl   = (const float*)d_in[9];
    const float* bl   = (const float*)d_in[10];
    float* out = (float*)d_out;
    float* score = out + (size_t)B * C * T;
    (void)bk;

    cudaFuncSetAttribute(gemm_qv_kernel,     cudaFuncAttributeMaxDynamicSharedMemorySize, SMEM_BYTES);
    cudaFuncSetAttribute(gemm_qk_kernel,     cudaFuncAttributeMaxDynamicSharedMemorySize, SMEM_BYTES);
    cudaFuncSetAttribute(gemm_av_kernel,     cudaFuncAttributeMaxDynamicSharedMemorySize, SMEM_BYTES);
    cudaFuncSetAttribute(gemm_smooth_kernel, cudaFuncAttributeMaxDynamicSharedMemorySize, SMEM_BYTES);

    wksum_kernel<<<2, 256>>>(Wk);
    transpose_kernel<<<dim3(T / 32, C / 32, B), dim3(32, 8)>>>(feat);
    convertw_kernel<<<(C * C + 255) / 256, 256>>>(Wq, Wv, Ws);

    gemm_qv_kernel<<<dim3(T / 128, C / 128, 2 * B), 256, SMEM_BYTES>>>(bq, bv);
    gemm_qk_kernel<<<dim3(T / 128, T / 128, B), 256, SMEM_BYTES>>>();
    softmax_kernel<<<B * T, 256>>>();
    gemm_av_kernel<<<dim3(C / 128, T / 128, B), 256, SMEM_BYTES>>>();

    vsum_kernel<<<dim3(C, B), 256>>>();
    vsumwl_kernel<<<B, 128>>>(Wl);
    score_kernel<<<B * T, 128>>>(Wl, bl, score);

    gemm_smooth_kernel<<<dim3(T / 128, C / 128, B), 256, SMEM_BYTES>>>(bs, feat, out);

    ln2_kernel<<<dim3((C * T) / 256, B), 256>>>(out);
}